// round 13
// baseline (speedup 1.0000x reference)
#include <cuda_runtime.h>
#include <cuda_bf16.h>
#include <cstdint>
#include <cstddef>
#include <math.h>

// Problem constants
#define B    32
#define S    64
#define T    64
#define E    512
#define H    1024
#define VT   32000
#define TWOE 1024
#define FOURH 4096
#define KSL  4            // K-slices for per-step W_hh GEMM; gpart slice KSL = encsum

// ---------------- scratch (device globals) ----------------
__device__ float g_enc[B * S * TWOE];                 // [b*S+s][1024]
__device__ float g_encmean[B * TWOE];
__device__ float g_h[B * H];
__device__ float g_c[B * H];
__device__ float g_attw[B * S];
__device__ float g_bsum[FOURH];
__device__ float g_gatesw[(size_t)B * T * FOURH];     // row r=t*B+b
__device__ float g_encprojT[(size_t)FOURH * B * S];   // [n][b*S+s]
__device__ float g_gpart[(KSL + 1) * B * FOURH];
// bf16 hi/lo operand buffers
__device__ __nv_bfloat16 g_encHi[(size_t)B * S * TWOE];
__device__ __nv_bfloat16 g_encLo[(size_t)B * S * TWOE];
__device__ __nv_bfloat16 g_wrdHi[(size_t)B * T * E];  // row r=t*B+b
__device__ __nv_bfloat16 g_wrdLo[(size_t)B * T * E];
__device__ __nv_bfloat16 g_hsHi[(size_t)B * T * H];   // row r=b*T+t
__device__ __nv_bfloat16 g_hsLo[(size_t)B * T * H];
__device__ __nv_bfloat16 g_WoHi[(size_t)VT * H];
__device__ __nv_bfloat16 g_WoLo[(size_t)VT * H];
__device__ __nv_bfloat16 g_WcHi[(size_t)FOURH * H];   // W_ih[:,512:1536]
__device__ __nv_bfloat16 g_WcLo[(size_t)FOURH * H];
__device__ __nv_bfloat16 g_WwHi[(size_t)FOURH * E];   // W_ih[:,0:512]
__device__ __nv_bfloat16 g_WwLo[(size_t)FOURH * E];

// ---------------- asm helpers ----------------
__device__ __forceinline__ uint32_t s2u(const void* p) {
    uint32_t a;
    asm("{ .reg .u64 t; cvta.to.shared.u64 t, %1; cvt.u32.u64 %0, t; }" : "=r"(a) : "l"(p));
    return a;
}
__device__ __forceinline__ void cp16(uint32_t saddr, const void* g) {
    asm volatile("cp.async.cg.shared.global [%0], [%1], 16;" :: "r"(saddr), "l"(g));
}
__device__ __forceinline__ void cp_commit() {
    asm volatile("cp.async.commit_group;" ::: "memory");
}
__device__ __forceinline__ void cp_wait2() {
    asm volatile("cp.async.wait_group 2;" ::: "memory");
}
__device__ __forceinline__ void ldsm_x4(uint32_t* r, uint32_t addr) {
    asm volatile("ldmatrix.sync.aligned.m8n8.x4.shared.b16 {%0,%1,%2,%3}, [%4];"
                 : "=r"(r[0]), "=r"(r[1]), "=r"(r[2]), "=r"(r[3]) : "r"(addr));
}
__device__ __forceinline__ void ldsm_x2(uint32_t* r, uint32_t addr) {
    asm volatile("ldmatrix.sync.aligned.m8n8.x2.shared.b16 {%0,%1}, [%2];"
                 : "=r"(r[0]), "=r"(r[1]) : "r"(addr));
}
__device__ __forceinline__ void mma16816(float* d, const uint32_t* a, const uint32_t* b) {
    asm volatile("mma.sync.aligned.m16n8k16.row.col.f32.bf16.bf16.f32 "
                 "{%0,%1,%2,%3}, {%4,%5,%6,%7}, {%8,%9}, {%0,%1,%2,%3};"
                 : "+f"(d[0]), "+f"(d[1]), "+f"(d[2]), "+f"(d[3])
                 : "r"(a[0]), "r"(a[1]), "r"(a[2]), "r"(a[3]), "r"(b[0]), "r"(b[1]));
}
// 16B-segment offset (row r, seg c 0..3) in a Nx32-bf16 tile; conflict-free ldmatrix phases
__device__ __forceinline__ uint32_t swz(int r, int c) {
    return (uint32_t)(r * 64 + ((((c + (r >> 2)) & 3) ^ (r & 3)) << 4));
}
__device__ __forceinline__ float sigm(float x) { return 1.f / (1.f + expf(-x)); }

// ---------------- prep kernels ----------------

__global__ void __launch_bounds__(256) k_prep_enc(const int* __restrict__ src,
                                                  const int* __restrict__ pos,
                                                  const float* __restrict__ enc_emb,
                                                  const float* __restrict__ pos_emb) {
    int bs = blockIdx.x;
    int w = src[bs], p = pos[bs];
    int j = threadIdx.x * 4;
    const float* sp = (j < 512) ? (enc_emb + (size_t)w * E + j)
                                : (pos_emb + (size_t)p * E + (j - 512));
    float4 v = *(const float4*)sp;
    size_t o = (size_t)bs * TWOE + j;
    *(float4*)(g_enc + o) = v;
    float a[4]; a[0] = v.x; a[1] = v.y; a[2] = v.z; a[3] = v.w;
    __nv_bfloat16 h4[4], l4[4];
    #pragma unroll
    for (int i = 0; i < 4; i++) {
        __nv_bfloat16 bh = __float2bfloat16_rn(a[i]);
        h4[i] = bh;
        l4[i] = __float2bfloat16_rn(a[i] - __bfloat162float(bh));
    }
    *(uint2*)(g_encHi + o) = *(uint2*)h4;
    *(uint2*)(g_encLo + o) = *(uint2*)l4;
}

__global__ void __launch_bounds__(128) k_prep_words(const int* __restrict__ ts,
                                                    const float* __restrict__ dec_emb) {
    int r = blockIdx.x;
    int t = r / B, b = r % B;
    int w = ts[b * T + t];
    int j = threadIdx.x * 4;
    float4 v = *(const float4*)(dec_emb + (size_t)w * E + j);
    float a[4]; a[0] = v.x; a[1] = v.y; a[2] = v.z; a[3] = v.w;
    __nv_bfloat16 h4[4], l4[4];
    #pragma unroll
    for (int i = 0; i < 4; i++) {
        __nv_bfloat16 bh = __float2bfloat16_rn(a[i]);
        h4[i] = bh;
        l4[i] = __float2bfloat16_rn(a[i] - __bfloat162float(bh));
    }
    size_t o = (size_t)r * E + j;
    *(uint2*)(g_wrdHi + o) = *(uint2*)h4;
    *(uint2*)(g_wrdLo + o) = *(uint2*)l4;
}

__global__ void k_cvt_rows(const float* __restrict__ src, int srcStride,
                           __nv_bfloat16* __restrict__ hi, __nv_bfloat16* __restrict__ lo,
                           int ncols) {
    int r = blockIdx.x;
    int j = threadIdx.x * 4;
    float4 v = *(const float4*)(src + (size_t)r * srcStride + j);
    float a[4]; a[0] = v.x; a[1] = v.y; a[2] = v.z; a[3] = v.w;
    __nv_bfloat16 h4[4], l4[4];
    #pragma unroll
    for (int i = 0; i < 4; i++) {
        __nv_bfloat16 bh = __float2bfloat16_rn(a[i]);
        h4[i] = bh;
        l4[i] = __float2bfloat16_rn(a[i] - __bfloat162float(bh));
    }
    size_t o = (size_t)r * ncols + j;
    *(uint2*)(hi + o) = *(uint2*)h4;
    *(uint2*)(lo + o) = *(uint2*)l4;
}

__global__ void __launch_bounds__(256) k_bsum(const float* __restrict__ b_ih,
                                              const float* __restrict__ b_hh) {
    int i = blockIdx.x * 256 + threadIdx.x;
    g_bsum[i] = b_ih[i] + b_hh[i];
}

__global__ void __launch_bounds__(1024) k_encmean() {
    int b = blockIdx.x, d = threadIdx.x;
    float s = 0.f;
    const float* base = g_enc + (size_t)b * S * TWOE + d;
    #pragma unroll 8
    for (int i = 0; i < S; i++) s += base[(size_t)i * TWOE];
    g_encmean[b * TWOE + d] = s * (1.0f / S);
}

__global__ void __launch_bounds__(256) k_h0(const float* __restrict__ W_h0,
                                            const float* __restrict__ b_h0) {
    int gid = blockIdx.x * 8 + (threadIdx.x >> 5);
    int lane = threadIdx.x & 31;
    int b = gid >> 10, n = gid & 1023;
    const float* a = g_encmean + b * 1024;
    const float* w = W_h0 + (size_t)n * 1024;
    float acc = 0.f;
    for (int k = lane; k < 1024; k += 32) acc += a[k] * w[k];
    #pragma unroll
    for (int o = 16; o; o >>= 1) acc += __shfl_xor_sync(0xffffffffu, acc, o);
    if (lane == 0) {
        float v = acc + b_h0[n];
        g_h[b * H + n] = v;
        g_c[b * H + n] = v;
    }
}

// ---------------- bf16 HMMA 3-pass GEMM, 2 CTAs/SM ----------------
// CTA: 128 threads (4 warps), tile M=64 x N=128, BK=32, 3-stage cp.async.
// Stage: Ahi(4KB) | Alo(4KB) | Bhi(8KB) | Blo(8KB) = 24KB; 3 stages = 72KB/CTA.
#define PSTG 24576
#define HMMA_SMEM (3 * PSTG)

__global__ void __launch_bounds__(128, 2) k_hmma(
    const __nv_bfloat16* __restrict__ Ahi, const __nv_bfloat16* __restrict__ Alo,
    const __nv_bfloat16* __restrict__ Bhi, const __nv_bfloat16* __restrict__ Blo,
    const float* __restrict__ bias, float* __restrict__ C, int K, int ldc)
{
    extern __shared__ __align__(128) char smem[];
    const uint32_t sb = s2u(smem);
    int tid = threadIdx.x, lane = tid & 31, wn = tid >> 5;   // warp = n-quadrant
    int m0 = blockIdx.x * 64;     // x fastest: consecutive CTAs share the B slice in L2
    int n0 = blockIdx.y * 128;
    int nIter = K >> 5;

    float acc[4][4][4];
    #pragma unroll
    for (int i = 0; i < 4; i++) {
        #pragma unroll
        for (int j = 0; j < 4; j++) {
            #pragma unroll
            for (int v = 0; v < 4; v++) acc[i][j][v] = 0.f;
        }
    }

    // loader: thread -> A row lr (2 segs), B rows lr & lr+64 (2 segs each)
    int lr = tid >> 1;             // 0..63
    int lc = (tid & 1) * 2;        // seg 0 or 2
    uint32_t as0 = swz(lr, lc),      as1 = swz(lr, lc + 1);
    uint32_t bs0 = swz(lr, lc),      bs1 = swz(lr, lc + 1);
    uint32_t bs2 = swz(lr + 64, lc), bs3 = swz(lr + 64, lc + 1);
    const char* gAh = (const char*)(Ahi + (size_t)(m0 + lr) * K) + lc * 16;
    const char* gAl = (const char*)(Alo + (size_t)(m0 + lr) * K) + lc * 16;
    const char* gBh0 = (const char*)(Bhi + (size_t)(n0 + lr) * K) + lc * 16;
    const char* gBh1 = (const char*)(Bhi + (size_t)(n0 + lr + 64) * K) + lc * 16;
    const char* gBl0 = (const char*)(Blo + (size_t)(n0 + lr) * K) + lc * 16;
    const char* gBl1 = (const char*)(Blo + (size_t)(n0 + lr + 64) * K) + lc * 16;

    #define ISSUE(ST, K0) do { uint32_t s0 = sb + (uint32_t)(ST) * PSTG; \
        size_t kb = (size_t)(K0) * 2; \
        cp16(s0 + as0,          gAh + kb);  cp16(s0 + as1,          gAh + kb + 16); \
        cp16(s0 + 4096  + as0,  gAl + kb);  cp16(s0 + 4096  + as1,  gAl + kb + 16); \
        cp16(s0 + 8192  + bs0,  gBh0 + kb); cp16(s0 + 8192  + bs1,  gBh0 + kb + 16); \
        cp16(s0 + 8192  + bs2,  gBh1 + kb); cp16(s0 + 8192  + bs3,  gBh1 + kb + 16); \
        cp16(s0 + 16384 + bs0,  gBl0 + kb); cp16(s0 + 16384 + bs1,  gBl0 + kb + 16); \
        cp16(s0 + 16384 + bs2,  gBl1 + kb); cp16(s0 + 16384 + bs3,  gBl1 + kb + 16); } while (0)

    ISSUE(0, 0);  cp_commit();
    ISSUE(1, 32); cp_commit();
    ISSUE(2, 64); cp_commit();    // K >= 96 always (512/1024 here)

    int arow = lane & 15;
    int aselh = lane >> 4;
    int brow = lane & 7;
    int bselh = (lane >> 3) & 1;

    for (int it = 0; it < nIter; ++it) {
        cp_wait2();
        __syncthreads();
        int st = it - (it / 3) * 3;
        uint32_t stA_hi = sb + (uint32_t)st * PSTG;
        uint32_t stA_lo = stA_hi + 4096;
        uint32_t stB_hi = stA_hi + 8192;
        uint32_t stB_lo = stA_hi + 16384;
        #pragma unroll
        for (int ks = 0; ks < 2; ++ks) {
            int c0 = ks * 2;
            uint32_t ah[4][4], al[4][4], bh[4][2], bl[4][2];
            #pragma unroll
            for (int mt = 0; mt < 4; mt++) {
                int r = mt * 16 + arow;
                uint32_t off = swz(r, c0 + aselh);
                ldsm_x4(ah[mt], stA_hi + off);
                ldsm_x4(al[mt], stA_lo + off);
            }
            #pragma unroll
            for (int nt = 0; nt < 4; nt++) {
                int r = wn * 32 + nt * 8 + brow;
                uint32_t off = swz(r, c0 + bselh);
                ldsm_x2(bh[nt], stB_hi + off);
                ldsm_x2(bl[nt], stB_lo + off);
            }
            #pragma unroll
            for (int mt = 0; mt < 4; mt++) {
                #pragma unroll
                for (int nt = 0; nt < 4; nt++) {
                    mma16816(acc[mt][nt], ah[mt], bh[nt]);
                    mma16816(acc[mt][nt], ah[mt], bl[nt]);
                    mma16816(acc[mt][nt], al[mt], bh[nt]);
                }
            }
        }
        __syncthreads();
        if (it + 3 < nIter) ISSUE(st, (it + 3) * 32);
        cp_commit();
    }
    #undef ISSUE

    #pragma unroll
    for (int nt = 0; nt < 4; nt++) {
        int col = n0 + wn * 32 + nt * 8 + (lane & 3) * 2;
        float b0 = 0.f, b1 = 0.f;
        if (bias) { b0 = bias[col]; b1 = bias[col + 1]; }
        #pragma unroll
        for (int mt = 0; mt < 4; mt++) {
            int row = m0 + mt * 16 + (lane >> 2);
            float* c0p = C + (size_t)row * ldc + col;
            float* c1p = C + (size_t)(row + 8) * ldc + col;
            c0p[0] = acc[mt][nt][0] + b0;
            c0p[1] = acc[mt][nt][1] + b1;
            c1p[0] = acc[mt][nt][2] + b0;
            c1p[1] = acc[mt][nt][3] + b1;
        }
    }
}

// ---------------- per-step kernels (R8 structure) ----------------

// grid (32, KSL+8).
__global__ void __launch_bounds__(256) k_gatesh(const float* __restrict__ W_hh) {
    int slice = blockIdx.y;
    int tid = threadIdx.x;

    if (slice >= KSL) {
        int b = blockIdx.x;
        int n0 = (slice - KSL) * 512;
        __shared__ float aw[S];
        if (tid < S) aw[tid] = g_attw[b * S + tid];
        __syncthreads();
        float* gp = g_gpart + (size_t)KSL * (B * FOURH) + (size_t)b * FOURH;
        #pragma unroll
        for (int half = 0; half < 2; half++) {
            int n = n0 + half * 256 + tid;
            const float4* ep = (const float4*)(g_encprojT + (size_t)n * (B * S) + b * S);
            float acc = 0.f;
            #pragma unroll
            for (int s4 = 0; s4 < 16; s4++) {
                float4 v = ep[s4];
                acc += aw[s4 * 4 + 0] * v.x + aw[s4 * 4 + 1] * v.y
                     + aw[s4 * 4 + 2] * v.z + aw[s4 * 4 + 3] * v.w;
            }
            gp[n] = acc;
        }
        return;
    }

    const int KC = 32;
    __shared__ float Xs[KC][36];
    __shared__ float Ws[KC][132];
    int n0 = blockIdx.x * 128;
    int k00 = slice * 256;
    int mg = tid >> 5;
    int ng = tid & 31;

    float acc[4][4];
    #pragma unroll
    for (int i = 0; i < 4; i++) {
        #pragma unroll
        for (int j = 0; j < 4; j++) acc[i][j] = 0.f;
    }

    int xr = tid >> 3;
    int xk = (tid & 7) << 2;

    for (int kc = k00; kc < k00 + 256; kc += KC) {
        float4 xv = *(const float4*)(g_h + (size_t)xr * H + kc + xk);
        float4 wv[4];
        #pragma unroll
        for (int p = 0; p < 4; p++) {
            int row = n0 + p * 32 + xr;
            wv[p] = *(const float4*)(W_hh + (size_t)row * H + kc + xk);
        }
        __syncthreads();
        Xs[xk + 0][xr] = xv.x; Xs[xk + 1][xr] = xv.y;
        Xs[xk + 2][xr] = xv.z; Xs[xk + 3][xr] = xv.w;
        #pragma unroll
        for (int p = 0; p < 4; p++) {
            Ws[xk + 0][p * 32 + xr] = wv[p].x;
            Ws[xk + 1][p * 32 + xr] = wv[p].y;
            Ws[xk + 2][p * 32 + xr] = wv[p].z;
            Ws[xk + 3][p * 32 + xr] = wv[p].w;
        }
        __syncthreads();
        #pragma unroll 8
        for (int kk = 0; kk < KC; kk++) {
            float xa[4], wf[4];
            *(float4*)xa = *(const float4*)&Xs[kk][mg * 4];
            *(float4*)wf = *(const float4*)&Ws[kk][ng * 4];
            #pragma unroll
            for (int i = 0; i < 4; i++) {
                #pragma unroll
                for (int j = 0; j < 4; j++)
                    acc[i][j] += xa[i] * wf[j];
            }
        }
    }
    float* gp = g_gpart + (size_t)slice * (B * FOURH);
    #pragma unroll
    for (int i = 0; i < 4; i++) {
        int m = mg * 4 + i;
        #pragma unroll
        for (int j = 0; j < 4; j++) {
            int n = n0 + ng * 4 + j;
            gp[(size_t)m * FOURH + n] = acc[i][j];
        }
    }
}

// fused LSTM pointwise (t>=0) + attention for next step. grid 32 (b), 1024 threads.
__global__ void __launch_bounds__(1024) k_lstm_attn(int t, const int* __restrict__ source_lengths) {
    int b = blockIdx.x;
    int n = threadIdx.x;
    __shared__ float sh[1024];
    __shared__ float se[64];

    if (t >= 0) {
        const float* gw = g_gatesw + ((size_t)t * B + b) * FOURH;
        float gi = gw[n], gf = gw[n + 1024], gg = gw[n + 2048], go = gw[n + 3072];
        #pragma unroll
        for (int s = 0; s < KSL + 1; s++) {
            const float* gp = g_gpart + (size_t)s * (B * FOURH) + (size_t)b * FOURH;
            gi += gp[n]; gf += gp[n + 1024]; gg += gp[n + 2048]; go += gp[n + 3072];
        }
        float c = g_c[b * H + n];
        float iv = sigm(gi), fv = sigm(gf), gv = tanhf(gg), ov = sigm(go);
        c = fv * c + iv * gv;
        float h = ov * tanhf(c);
        g_c[b * H + n] = c;
        g_h[b * H + n] = h;
        sh[n] = h;
        size_t row = ((size_t)b * T + t) * H + n;
        __nv_bfloat16 hh = __float2bfloat16_rn(h);
        g_hsHi[row] = hh;
        g_hsLo[row] = __float2bfloat16_rn(h - __bfloat162float(hh));
    } else {
        sh[n] = g_h[b * H + n];
    }
    __syncthreads();

    int warp = n >> 5, lane = n & 31;
    #pragma unroll
    for (int q = 0; q < 2; q++) {
        int s = warp * 2 + q;
        const float* er = g_enc + ((size_t)b * S + s) * TWOE;
        float acc = 0.f;
        #pragma unroll 8
        for (int k = lane; k < TWOE; k += 32) acc += er[k] * sh[k];
        #pragma unroll
        for (int o = 16; o; o >>= 1) acc += __shfl_xor_sync(0xffffffffu, acc, o);
        if (lane == 0) se[s] = acc;
    }
    __syncthreads();
    if (warp == 0) {
        int len = source_lengths[b];
        float e0 = se[lane], e1 = se[lane + 32];
        float m = fmaxf(e0, e1);
        #pragma unroll
        for (int o = 16; o; o >>= 1) m = fmaxf(m, __shfl_xor_sync(0xffffffffu, m, o));
        float p0 = (lane < len)      ? expf(e0 - m) : 0.f;
        float p1 = (lane + 32 < len) ? expf(e1 - m) : 0.f;
        float ssum = p0 + p1;
        #pragma unroll
        for (int o = 16; o; o >>= 1) ssum += __shfl_xor_sync(0xffffffffu, ssum, o);
        float inv = 1.f / ssum;
        g_attw[b * S + lane] = p0 * inv;
        g_attw[b * S + lane + 32] = p1 * inv;
    }
}

// ---------------- host ----------------
extern "C" void kernel_launch(void* const* d_in, const int* in_sizes, int n_in,
                              void* d_out, int out_size) {
    int p = 0;
    auto nx = [&]() -> const void* {
        while (p < n_in && in_sizes[p] == 1) p++;
        return d_in[p++];
    };
    const int*   ts      = (const int*)nx();
    (void)nx();                                  // target_lengths (unused)
    const int*   sl      = (const int*)nx();
    const int*   ss      = (const int*)nx();
    const int*   pos     = (const int*)nx();
    const float* enc_emb = (const float*)nx();
    const float* pos_emb = (const float*)nx();
    const float* dec_emb = (const float*)nx();
    const float* W_h0    = (const float*)nx();
    const float* b_h0    = (const float*)nx();
    const float* W_ih    = (const float*)nx();
    const float* W_hh    = (const float*)nx();
    const float* b_ih    = (const float*)nx();
    const float* b_hh    = (const float*)nx();
    const float* W_out   = (const float*)nx();
    const float* b_out   = (const float*)nx();

    float *p_gatesw, *p_encprojT, *p_bsum;
    __nv_bfloat16 *p_encHi, *p_encLo, *p_wrdHi, *p_wrdLo, *p_hsHi, *p_hsLo;
    __nv_bfloat16 *p_WoHi, *p_WoLo, *p_WcHi, *p_WcLo, *p_WwHi, *p_WwLo;
    cudaGetSymbolAddress((void**)&p_gatesw,   g_gatesw);
    cudaGetSymbolAddress((void**)&p_encprojT, g_encprojT);
    cudaGetSymbolAddress((void**)&p_bsum,     g_bsum);
    cudaGetSymbolAddress((void**)&p_encHi,    g_encHi);
    cudaGetSymbolAddress((void**)&p_encLo,    g_encLo);
    cudaGetSymbolAddress((void**)&p_wrdHi,    g_wrdHi);
    cudaGetSymbolAddress((void**)&p_wrdLo,    g_wrdLo);
    cudaGetSymbolAddress((void**)&p_hsHi,     g_hsHi);
    cudaGetSymbolAddress((void**)&p_hsLo,     g_hsLo);
    cudaGetSymbolAddress((void**)&p_WoHi,     g_WoHi);
    cudaGetSymbolAddress((void**)&p_WoLo,     g_WoLo);
    cudaGetSymbolAddress((void**)&p_WcHi,     g_WcHi);
    cudaGetSymbolAddress((void**)&p_WcLo,     g_WcLo);
    cudaGetSymbolAddress((void**)&p_WwHi,     g_WwHi);
    cudaGetSymbolAddress((void**)&p_WwLo,     g_WwLo);

    cudaFuncSetAttribute(k_hmma, cudaFuncAttributeMaxDynamicSharedMemorySize, HMMA_SMEM);

    // ---- prep ----
    k_prep_enc  <<<B * S, 256>>>(ss, pos, enc_emb, pos_emb);
    k_prep_words<<<B * T, 128>>>(ts, dec_emb);
    k_cvt_rows  <<<VT, 256>>>(W_out, H, p_WoHi, p_WoLo, H);
    k_cvt_rows  <<<FOURH, 256>>>(W_ih + 512, 1536, p_WcHi, p_WcLo, H);
    k_cvt_rows  <<<FOURH, 128>>>(W_ih, 1536, p_WwHi, p_WwLo, E);
    k_bsum      <<<FOURH / 256, 256>>>(b_ih, b_hh);
    k_encmean   <<<B, 1024>>>();
    k_h0        <<<(B * H) / 8, 256>>>(W_h0, b_h0);
    // gates_w = words @ W_ih[:,:512]^T + (b_ih + b_hh)    [2048 x 4096], K=512
    k_hmma<<<dim3((B * T) / 64, FOURH / 128), 128, HMMA_SMEM>>>(
        p_wrdHi, p_wrdLo, p_WwHi, p_WwLo, p_bsum, p_gatesw, E, FOURH);
    // encprojT[n][bs] = W_ctx @ enc^T    [4096 x 2048], K=1024
    k_hmma<<<dim3(FOURH / 64, (B * S) / 128), 128, HMMA_SMEM>>>(
        p_WcHi, p_WcLo, p_encHi, p_encLo, nullptr, p_encprojT, H, B * S);
    // initial attention from h0
    k_lstm_attn<<<B, 1024>>>(-1, sl);

    // ---- sequential phase: 2 launches per step ----
    for (int t = 0; t < T; t++) {
        k_gatesh   <<<dim3(32, KSL + 8), 256>>>(W_hh);
        k_lstm_attn<<<B, 1024>>>(t, sl);
    }

    // ---- output projection: hs @ W_out^T + b_out   [2048 x 32000], K=1024 ----
    k_hmma<<<dim3((B * T) / 64, VT / 128), 128, HMMA_SMEM>>>(
        p_hsHi, p_hsLo, p_WoHi, p_WoLo, b_out, (float*)d_out, H, VT);
}

// round 15
// speedup vs baseline: 1.5594x; 1.5594x over previous
#include <cuda_runtime.h>
#include <cuda_bf16.h>
#include <cstdint>
#include <cstddef>
#include <math.h>

// Problem constants
#define B    32
#define S    64
#define T    64
#define E    512
#define H    1024
#define VT   32000
#define TWOE 1024
#define FOURH 4096
#define KSL  4            // K-slices for per-step W_hh GEMM; gpart slice KSL = encsum

// ---------------- scratch (device globals) ----------------
__device__ float g_enc[B * S * TWOE];                 // [b*S+s][1024]
__device__ float g_encmean[B * TWOE];
__device__ float g_h[B * H];
__device__ float g_c[B * H];
__device__ float g_attw[B * S];
__device__ float g_bsum[FOURH];
__device__ float g_gatesw[(size_t)B * T * FOURH];     // row r=t*B+b
__device__ float g_encprojT[(size_t)FOURH * B * S];   // [n][b*S+s]
__device__ float g_gpart[(KSL + 1) * B * FOURH];
// bf16 hi/lo operand buffers
__device__ __nv_bfloat16 g_encHi[(size_t)B * S * TWOE];
__device__ __nv_bfloat16 g_encLo[(size_t)B * S * TWOE];
__device__ __nv_bfloat16 g_wrdHi[(size_t)B * T * E];  // row r=t*B+b
__device__ __nv_bfloat16 g_wrdLo[(size_t)B * T * E];
__device__ __nv_bfloat16 g_hsHi[(size_t)B * T * H];   // row r=b*T+t
__device__ __nv_bfloat16 g_hsLo[(size_t)B * T * H];
__device__ __nv_bfloat16 g_WoHi[(size_t)VT * H];
__device__ __nv_bfloat16 g_WoLo[(size_t)VT * H];
__device__ __nv_bfloat16 g_WcHi[(size_t)FOURH * H];   // W_ih[:,512:1536]
__device__ __nv_bfloat16 g_WcLo[(size_t)FOURH * H];
__device__ __nv_bfloat16 g_WwHi[(size_t)FOURH * E];   // W_ih[:,0:512]
__device__ __nv_bfloat16 g_WwLo[(size_t)FOURH * E];

// ---------------- asm helpers ----------------
__device__ __forceinline__ uint32_t s2u(const void* p) {
    uint32_t a;
    asm("{ .reg .u64 t; cvta.to.shared.u64 t, %1; cvt.u32.u64 %0, t; }" : "=r"(a) : "l"(p));
    return a;
}
__device__ __forceinline__ void cp16(uint32_t saddr, const void* g) {
    asm volatile("cp.async.cg.shared.global [%0], [%1], 16;" :: "r"(saddr), "l"(g));
}
__device__ __forceinline__ void cp_commit() {
    asm volatile("cp.async.commit_group;" ::: "memory");
}
__device__ __forceinline__ void cp_wait2() {
    asm volatile("cp.async.wait_group 2;" ::: "memory");
}
__device__ __forceinline__ void ldsm_x4(uint32_t* r, uint32_t addr) {
    asm volatile("ldmatrix.sync.aligned.m8n8.x4.shared.b16 {%0,%1,%2,%3}, [%4];"
                 : "=r"(r[0]), "=r"(r[1]), "=r"(r[2]), "=r"(r[3]) : "r"(addr));
}
__device__ __forceinline__ void ldsm_x2(uint32_t* r, uint32_t addr) {
    asm volatile("ldmatrix.sync.aligned.m8n8.x2.shared.b16 {%0,%1}, [%2];"
                 : "=r"(r[0]), "=r"(r[1]) : "r"(addr));
}
__device__ __forceinline__ void mma16816(float* d, const uint32_t* a, const uint32_t* b) {
    asm volatile("mma.sync.aligned.m16n8k16.row.col.f32.bf16.bf16.f32 "
                 "{%0,%1,%2,%3}, {%4,%5,%6,%7}, {%8,%9}, {%0,%1,%2,%3};"
                 : "+f"(d[0]), "+f"(d[1]), "+f"(d[2]), "+f"(d[3])
                 : "r"(a[0]), "r"(a[1]), "r"(a[2]), "r"(a[3]), "r"(b[0]), "r"(b[1]));
}
// 16B-segment offset (row r, seg c 0..3) in a Nx32-bf16 tile; conflict-free ldmatrix phases
__device__ __forceinline__ uint32_t swz(int r, int c) {
    return (uint32_t)(r * 64 + ((((c + (r >> 2)) & 3) ^ (r & 3)) << 4));
}
__device__ __forceinline__ float sigm(float x) { return 1.f / (1.f + expf(-x)); }

// ---------------- prep kernels ----------------

__global__ void __launch_bounds__(256) k_prep_enc(const int* __restrict__ src,
                                                  const int* __restrict__ pos,
                                                  const float* __restrict__ enc_emb,
                                                  const float* __restrict__ pos_emb) {
    int bs = blockIdx.x;
    int w = src[bs], p = pos[bs];
    int j = threadIdx.x * 4;
    const float* sp = (j < 512) ? (enc_emb + (size_t)w * E + j)
                                : (pos_emb + (size_t)p * E + (j - 512));
    float4 v = *(const float4*)sp;
    size_t o = (size_t)bs * TWOE + j;
    *(float4*)(g_enc + o) = v;
    float a[4]; a[0] = v.x; a[1] = v.y; a[2] = v.z; a[3] = v.w;
    __nv_bfloat16 h4[4], l4[4];
    #pragma unroll
    for (int i = 0; i < 4; i++) {
        __nv_bfloat16 bh = __float2bfloat16_rn(a[i]);
        h4[i] = bh;
        l4[i] = __float2bfloat16_rn(a[i] - __bfloat162float(bh));
    }
    *(uint2*)(g_encHi + o) = *(uint2*)h4;
    *(uint2*)(g_encLo + o) = *(uint2*)l4;
}

__global__ void __launch_bounds__(128) k_prep_words(const int* __restrict__ ts,
                                                    const float* __restrict__ dec_emb) {
    int r = blockIdx.x;
    int t = r / B, b = r % B;
    int w = ts[b * T + t];
    int j = threadIdx.x * 4;
    float4 v = *(const float4*)(dec_emb + (size_t)w * E + j);
    float a[4]; a[0] = v.x; a[1] = v.y; a[2] = v.z; a[3] = v.w;
    __nv_bfloat16 h4[4], l4[4];
    #pragma unroll
    for (int i = 0; i < 4; i++) {
        __nv_bfloat16 bh = __float2bfloat16_rn(a[i]);
        h4[i] = bh;
        l4[i] = __float2bfloat16_rn(a[i] - __bfloat162float(bh));
    }
    size_t o = (size_t)r * E + j;
    *(uint2*)(g_wrdHi + o) = *(uint2*)h4;
    *(uint2*)(g_wrdLo + o) = *(uint2*)l4;
}

__global__ void k_cvt_rows(const float* __restrict__ src, int srcStride,
                           __nv_bfloat16* __restrict__ hi, __nv_bfloat16* __restrict__ lo,
                           int ncols) {
    int r = blockIdx.x;
    int j = threadIdx.x * 4;
    float4 v = *(const float4*)(src + (size_t)r * srcStride + j);
    float a[4]; a[0] = v.x; a[1] = v.y; a[2] = v.z; a[3] = v.w;
    __nv_bfloat16 h4[4], l4[4];
    #pragma unroll
    for (int i = 0; i < 4; i++) {
        __nv_bfloat16 bh = __float2bfloat16_rn(a[i]);
        h4[i] = bh;
        l4[i] = __float2bfloat16_rn(a[i] - __bfloat162float(bh));
    }
    size_t o = (size_t)r * ncols + j;
    *(uint2*)(hi + o) = *(uint2*)h4;
    *(uint2*)(lo + o) = *(uint2*)l4;
}

__global__ void __launch_bounds__(256) k_bsum(const float* __restrict__ b_ih,
                                              const float* __restrict__ b_hh) {
    int i = blockIdx.x * 256 + threadIdx.x;
    g_bsum[i] = b_ih[i] + b_hh[i];
}

__global__ void __launch_bounds__(1024) k_encmean() {
    int b = blockIdx.x, d = threadIdx.x;
    float s = 0.f;
    const float* base = g_enc + (size_t)b * S * TWOE + d;
    #pragma unroll 8
    for (int i = 0; i < S; i++) s += base[(size_t)i * TWOE];
    g_encmean[b * TWOE + d] = s * (1.0f / S);
}

__global__ void __launch_bounds__(256) k_h0(const float* __restrict__ W_h0,
                                            const float* __restrict__ b_h0) {
    int gid = blockIdx.x * 8 + (threadIdx.x >> 5);
    int lane = threadIdx.x & 31;
    int b = gid >> 10, n = gid & 1023;
    const float* a = g_encmean + b * 1024;
    const float* w = W_h0 + (size_t)n * 1024;
    float acc = 0.f;
    for (int k = lane; k < 1024; k += 32) acc += a[k] * w[k];
    #pragma unroll
    for (int o = 16; o; o >>= 1) acc += __shfl_xor_sync(0xffffffffu, acc, o);
    if (lane == 0) {
        float v = acc + b_h0[n];
        g_h[b * H + n] = v;
        g_c[b * H + n] = v;
    }
}

// ---------------- bf16 HMMA 3-pass GEMM, 2 CTAs/SM ----------------
// CTA: 128 threads (4 warps), tile M=64 x N=128, BK=32, 3-stage cp.async.
// Stage: Ahi(4KB) | Alo(4KB) | Bhi(8KB) | Blo(8KB) = 24KB; 3 stages = 72KB/CTA.
#define PSTG 24576
#define HMMA_SMEM (3 * PSTG)

__global__ void __launch_bounds__(128, 2) k_hmma(
    const __nv_bfloat16* __restrict__ Ahi, const __nv_bfloat16* __restrict__ Alo,
    const __nv_bfloat16* __restrict__ Bhi, const __nv_bfloat16* __restrict__ Blo,
    const float* __restrict__ bias, float* __restrict__ C, int K, int ldc)
{
    extern __shared__ __align__(128) char smem[];
    const uint32_t sb = s2u(smem);
    int tid = threadIdx.x, lane = tid & 31, wn = tid >> 5;   // warp = n-quadrant
    int m0 = blockIdx.x * 64;     // x fastest: consecutive CTAs share the B slice in L2
    int n0 = blockIdx.y * 128;
    int nIter = K >> 5;

    float acc[4][4][4];
    #pragma unroll
    for (int i = 0; i < 4; i++) {
        #pragma unroll
        for (int j = 0; j < 4; j++) {
            #pragma unroll
            for (int v = 0; v < 4; v++) acc[i][j][v] = 0.f;
        }
    }

    // loader: thread -> A row lr (2 segs), B rows lr & lr+64 (2 segs each)
    int lr = tid >> 1;             // 0..63
    int lc = (tid & 1) * 2;        // seg 0 or 2
    uint32_t as0 = swz(lr, lc),      as1 = swz(lr, lc + 1);
    uint32_t bs0 = swz(lr, lc),      bs1 = swz(lr, lc + 1);
    uint32_t bs2 = swz(lr + 64, lc), bs3 = swz(lr + 64, lc + 1);
    const char* gAh = (const char*)(Ahi + (size_t)(m0 + lr) * K) + lc * 16;
    const char* gAl = (const char*)(Alo + (size_t)(m0 + lr) * K) + lc * 16;
    const char* gBh0 = (const char*)(Bhi + (size_t)(n0 + lr) * K) + lc * 16;
    const char* gBh1 = (const char*)(Bhi + (size_t)(n0 + lr + 64) * K) + lc * 16;
    const char* gBl0 = (const char*)(Blo + (size_t)(n0 + lr) * K) + lc * 16;
    const char* gBl1 = (const char*)(Blo + (size_t)(n0 + lr + 64) * K) + lc * 16;

    #define ISSUE(ST, K0) do { uint32_t s0 = sb + (uint32_t)(ST) * PSTG; \
        size_t kb = (size_t)(K0) * 2; \
        cp16(s0 + as0,          gAh + kb);  cp16(s0 + as1,          gAh + kb + 16); \
        cp16(s0 + 4096  + as0,  gAl + kb);  cp16(s0 + 4096  + as1,  gAl + kb + 16); \
        cp16(s0 + 8192  + bs0,  gBh0 + kb); cp16(s0 + 8192  + bs1,  gBh0 + kb + 16); \
        cp16(s0 + 8192  + bs2,  gBh1 + kb); cp16(s0 + 8192  + bs3,  gBh1 + kb + 16); \
        cp16(s0 + 16384 + bs0,  gBl0 + kb); cp16(s0 + 16384 + bs1,  gBl0 + kb + 16); \
        cp16(s0 + 16384 + bs2,  gBl1 + kb); cp16(s0 + 16384 + bs3,  gBl1 + kb + 16); } while (0)

    ISSUE(0, 0);  cp_commit();
    ISSUE(1, 32); cp_commit();
    ISSUE(2, 64); cp_commit();    // K >= 96 always (512/1024 here)

    int arow = lane & 15;
    int aselh = lane >> 4;
    int brow = lane & 7;
    int bselh = (lane >> 3) & 1;

    for (int it = 0; it < nIter; ++it) {
        cp_wait2();
        __syncthreads();
        int st = it - (it / 3) * 3;
        uint32_t stA_hi = sb + (uint32_t)st * PSTG;
        uint32_t stA_lo = stA_hi + 4096;
        uint32_t stB_hi = stA_hi + 8192;
        uint32_t stB_lo = stA_hi + 16384;
        #pragma unroll
        for (int ks = 0; ks < 2; ++ks) {
            int c0 = ks * 2;
            uint32_t ah[4][4], al[4][4], bh[4][2], bl[4][2];
            #pragma unroll
            for (int mt = 0; mt < 4; mt++) {
                int r = mt * 16 + arow;
                uint32_t off = swz(r, c0 + aselh);
                ldsm_x4(ah[mt], stA_hi + off);
                ldsm_x4(al[mt], stA_lo + off);
            }
            #pragma unroll
            for (int nt = 0; nt < 4; nt++) {
                int r = wn * 32 + nt * 8 + brow;
                uint32_t off = swz(r, c0 + bselh);
                ldsm_x2(bh[nt], stB_hi + off);
                ldsm_x2(bl[nt], stB_lo + off);
            }
            #pragma unroll
            for (int mt = 0; mt < 4; mt++) {
                #pragma unroll
                for (int nt = 0; nt < 4; nt++) {
                    mma16816(acc[mt][nt], ah[mt], bh[nt]);
                    mma16816(acc[mt][nt], ah[mt], bl[nt]);
                    mma16816(acc[mt][nt], al[mt], bh[nt]);
                }
            }
        }
        __syncthreads();
        if (it + 3 < nIter) ISSUE(st, (it + 3) * 32);
        cp_commit();
    }
    #undef ISSUE

    #pragma unroll
    for (int nt = 0; nt < 4; nt++) {
        int col = n0 + wn * 32 + nt * 8 + (lane & 3) * 2;
        float b0 = 0.f, b1 = 0.f;
        if (bias) { b0 = bias[col]; b1 = bias[col + 1]; }
        #pragma unroll
        for (int mt = 0; mt < 4; mt++) {
            int row = m0 + mt * 16 + (lane >> 2);
            float* c0p = C + (size_t)row * ldc + col;
            float* c1p = C + (size_t)(row + 8) * ldc + col;
            c0p[0] = acc[mt][nt][0] + b0;
            c0p[1] = acc[mt][nt][1] + b1;
            c1p[0] = acc[mt][nt][2] + b0;
            c1p[1] = acc[mt][nt][3] + b1;
        }
    }
}

// ---------------- per-step kernels (R8 structure) ----------------

// grid (32, KSL+8).
__global__ void __launch_bounds__(256) k_gatesh(const float* __restrict__ W_hh) {
    int slice = blockIdx.y;
    int tid = threadIdx.x;

    if (slice >= KSL) {
        int b = blockIdx.x;
        int n0 = (slice - KSL) * 512;
        __shared__ float aw[S];
        if (tid < S) aw[tid] = g_attw[b * S + tid];
        __syncthreads();
        float* gp = g_gpart + (size_t)KSL * (B * FOURH) + (size_t)b * FOURH;
        #pragma unroll
        for (int half = 0; half < 2; half++) {
            int n = n0 + half * 256 + tid;
            const float4* ep = (const float4*)(g_encprojT + (size_t)n * (B * S) + b * S);
            float acc = 0.f;
            #pragma unroll
            for (int s4 = 0; s4 < 16; s4++) {
                float4 v = ep[s4];
                acc += aw[s4 * 4 + 0] * v.x + aw[s4 * 4 + 1] * v.y
                     + aw[s4 * 4 + 2] * v.z + aw[s4 * 4 + 3] * v.w;
            }
            gp[n] = acc;
        }
        return;
    }

    const int KC = 32;
    __shared__ float Xs[KC][36];
    __shared__ float Ws[KC][132];
    int n0 = blockIdx.x * 128;
    int k00 = slice * 256;
    int mg = tid >> 5;
    int ng = tid & 31;

    float acc[4][4];
    #pragma unroll
    for (int i = 0; i < 4; i++) {
        #pragma unroll
        for (int j = 0; j < 4; j++) acc[i][j] = 0.f;
    }

    int xr = tid >> 3;
    int xk = (tid & 7) << 2;

    for (int kc = k00; kc < k00 + 256; kc += KC) {
        float4 xv = *(const float4*)(g_h + (size_t)xr * H + kc + xk);
        float4 wv[4];
        #pragma unroll
        for (int p = 0; p < 4; p++) {
            int row = n0 + p * 32 + xr;
            wv[p] = *(const float4*)(W_hh + (size_t)row * H + kc + xk);
        }
        __syncthreads();
        Xs[xk + 0][xr] = xv.x; Xs[xk + 1][xr] = xv.y;
        Xs[xk + 2][xr] = xv.z; Xs[xk + 3][xr] = xv.w;
        #pragma unroll
        for (int p = 0; p < 4; p++) {
            Ws[xk + 0][p * 32 + xr] = wv[p].x;
            Ws[xk + 1][p * 32 + xr] = wv[p].y;
            Ws[xk + 2][p * 32 + xr] = wv[p].z;
            Ws[xk + 3][p * 32 + xr] = wv[p].w;
        }
        __syncthreads();
        #pragma unroll 8
        for (int kk = 0; kk < KC; kk++) {
            float xa[4], wf[4];
            *(float4*)xa = *(const float4*)&Xs[kk][mg * 4];
            *(float4*)wf = *(const float4*)&Ws[kk][ng * 4];
            #pragma unroll
            for (int i = 0; i < 4; i++) {
                #pragma unroll
                for (int j = 0; j < 4; j++)
                    acc[i][j] += xa[i] * wf[j];
            }
        }
    }
    float* gp = g_gpart + (size_t)slice * (B * FOURH);
    #pragma unroll
    for (int i = 0; i < 4; i++) {
        int m = mg * 4 + i;
        #pragma unroll
        for (int j = 0; j < 4; j++) {
            int n = n0 + ng * 4 + j;
            gp[(size_t)m * FOURH + n] = acc[i][j];
        }
    }
}

// fused LSTM pointwise (t>=0) + attention for next step. grid 32 (b), 1024 threads.
__global__ void __launch_bounds__(1024) k_lstm_attn(int t, const int* __restrict__ source_lengths) {
    int b = blockIdx.x;
    int n = threadIdx.x;
    __shared__ float sh[1024];
    __shared__ float se[64];

    if (t >= 0) {
        const float* gw = g_gatesw + ((size_t)t * B + b) * FOURH;
        float gi = gw[n], gf = gw[n + 1024], gg = gw[n + 2048], go = gw[n + 3072];
        #pragma unroll
        for (int s = 0; s < KSL + 1; s++) {
            const float* gp = g_gpart + (size_t)s * (B * FOURH) + (size_t)b * FOURH;
            gi += gp[n]; gf += gp[n + 1024]; gg += gp[n + 2048]; go += gp[n + 3072];
        }
        float c = g_c[b * H + n];
        float iv = sigm(gi), fv = sigm(gf), gv = tanhf(gg), ov = sigm(go);
        c = fv * c + iv * gv;
        float h = ov * tanhf(c);
        g_c[b * H + n] = c;
        g_h[b * H + n] = h;
        sh[n] = h;
        size_t row = ((size_t)b * T + t) * H + n;
        __nv_bfloat16 hh = __float2bfloat16_rn(h);
        g_hsHi[row] = hh;
        g_hsLo[row] = __float2bfloat16_rn(h - __bfloat162float(hh));
    } else {
        sh[n] = g_h[b * H + n];
    }
    __syncthreads();

    int warp = n >> 5, lane = n & 31;
    #pragma unroll
    for (int q = 0; q < 2; q++) {
        int s = warp * 2 + q;
        const float* er = g_enc + ((size_t)b * S + s) * TWOE;
        float acc = 0.f;
        #pragma unroll 8
        for (int k = lane; k < TWOE; k += 32) acc += er[k] * sh[k];
        #pragma unroll
        for (int o = 16; o; o >>= 1) acc += __shfl_xor_sync(0xffffffffu, acc, o);
        if (lane == 0) se[s] = acc;
    }
    __syncthreads();
    if (warp == 0) {
        int len = source_lengths[b];
        float e0 = se[lane], e1 = se[lane + 32];
        float m = fmaxf(e0, e1);
        #pragma unroll
        for (int o = 16; o; o >>= 1) m = fmaxf(m, __shfl_xor_sync(0xffffffffu, m, o));
        float p0 = (lane < len)      ? expf(e0 - m) : 0.f;
        float p1 = (lane + 32 < len) ? expf(e1 - m) : 0.f;
        float ssum = p0 + p1;
        #pragma unroll
        for (int o = 16; o; o >>= 1) ssum += __shfl_xor_sync(0xffffffffu, ssum, o);
        float inv = 1.f / ssum;
        g_attw[b * S + lane] = p0 * inv;
        g_attw[b * S + lane + 32] = p1 * inv;
    }
}

// ---------------- host ----------------
extern "C" void kernel_launch(void* const* d_in, const int* in_sizes, int n_in,
                              void* d_out, int out_size) {
    int p = 0;
    auto nx = [&]() -> const void* {
        while (p < n_in && in_sizes[p] == 1) p++;
        return d_in[p++];
    };
    const int*   ts      = (const int*)nx();
    (void)nx();                                  // target_lengths (unused)
    const int*   sl      = (const int*)nx();
    const int*   ss      = (const int*)nx();
    const int*   pos     = (const int*)nx();
    const float* enc_emb = (const float*)nx();
    const float* pos_emb = (const float*)nx();
    const float* dec_emb = (const float*)nx();
    const float* W_h0    = (const float*)nx();
    const float* b_h0    = (const float*)nx();
    const float* W_ih    = (const float*)nx();
    const float* W_hh    = (const float*)nx();
    const float* b_ih    = (const float*)nx();
    const float* b_hh    = (const float*)nx();
    const float* W_out   = (const float*)nx();
    const float* b_out   = (const float*)nx();

    float *p_gatesw, *p_encprojT, *p_bsum;
    __nv_bfloat16 *p_encHi, *p_encLo, *p_wrdHi, *p_wrdLo, *p_hsHi, *p_hsLo;
    __nv_bfloat16 *p_WoHi, *p_WoLo, *p_WcHi, *p_WcLo, *p_WwHi, *p_WwLo;
    cudaGetSymbolAddress((void**)&p_gatesw,   g_gatesw);
    cudaGetSymbolAddress((void**)&p_encprojT, g_encprojT);
    cudaGetSymbolAddress((void**)&p_bsum,     g_bsum);
    cudaGetSymbolAddress((void**)&p_encHi,    g_encHi);
    cudaGetSymbolAddress((void**)&p_encLo,    g_encLo);
    cudaGetSymbolAddress((void**)&p_wrdHi,    g_wrdHi);
    cudaGetSymbolAddress((void**)&p_wrdLo,    g_wrdLo);
    cudaGetSymbolAddress((void**)&p_hsHi,     g_hsHi);
    cudaGetSymbolAddress((void**)&p_hsLo,     g_hsLo);
    cudaGetSymbolAddress((void**)&p_WoHi,     g_WoHi);
    cudaGetSymbolAddress((void**)&p_WoLo,     g_WoLo);
    cudaGetSymbolAddress((void**)&p_WcHi,     g_WcHi);
    cudaGetSymbolAddress((void**)&p_WcLo,     g_WcLo);
    cudaGetSymbolAddress((void**)&p_WwHi,     g_WwHi);
    cudaGetSymbolAddress((void**)&p_WwLo,     g_WwLo);

    cudaFuncSetAttribute(k_hmma, cudaFuncAttributeMaxDynamicSharedMemorySize, HMMA_SMEM);

    // ---- prep ----
    k_prep_enc  <<<B * S, 256>>>(ss, pos, enc_emb, pos_emb);
    k_prep_words<<<B * T, 128>>>(ts, dec_emb);
    k_cvt_rows  <<<VT, 256>>>(W_out, H, p_WoHi, p_WoLo, H);
    k_cvt_rows  <<<FOURH, 256>>>(W_ih + 512, 1536, p_WcHi, p_WcLo, H);
    k_cvt_rows  <<<FOURH, 128>>>(W_ih, 1536, p_WwHi, p_WwLo, E);
    k_bsum      <<<FOURH / 256, 256>>>(b_ih, b_hh);
    k_encmean   <<<B, 1024>>>();
    k_h0        <<<(B * H) / 8, 256>>>(W_h0, b_h0);
    // gates_w = words @ W_ih[:,:512]^T + (b_ih + b_hh)    [2048 x 4096], K=512
    k_hmma<<<dim3((B * T) / 64, FOURH / 128), 128, HMMA_SMEM>>>(
        p_wrdHi, p_wrdLo, p_WwHi, p_WwLo, p_bsum, p_gatesw, E, FOURH);
    // encprojT[n][bs] = W_ctx @ enc^T    [4096 x 2048], K=1024
    k_hmma<<<dim3(FOURH / 64, (B * S) / 128), 128, HMMA_SMEM>>>(
        p_WcHi, p_WcLo, p_encHi, p_encLo, nullptr, p_encprojT, H, B * S);
    // initial attention from h0
    k_lstm_attn<<<B, 1024>>>(-1, sl);

    // ---- sequential phase: 2 launches per step ----
    for (int t = 0; t < T; t++) {
        k_gatesh   <<<dim3(32, KSL + 8), 256>>>(W_hh);
        k_lstm_attn<<<B, 1024>>>(t, sl);
    }

    // ---- output projection: hs @ W_out^T + b_out   [2048 x 32000], K=1024 ----
    k_hmma<<<dim3((B * T) / 64, VT / 128), 128, HMMA_SMEM>>>(
        p_hsHi, p_hsLo, p_WoHi, p_WoLo, b_out, (float*)d_out, H, VT);
}

// round 17
// speedup vs baseline: 1.6468x; 1.0561x over previous
#include <cuda_runtime.h>
#include <cuda_bf16.h>
#include <cstdint>
#include <cstddef>
#include <math.h>

// Problem constants
#define B    32
#define S    64
#define T    64
#define E    512
#define H    1024
#define VT   32000
#define TWOE 1024
#define FOURH 4096
#define KSL  4            // K-slices for per-step W_hh GEMM; gpart slice KSL = encsum

// ---------------- scratch (device globals) ----------------
__device__ float g_enc[B * S * TWOE];                 // [b*S+s][1024]
__device__ float g_encmean[B * TWOE];
__device__ float g_h[B * H];
__device__ float g_c[B * H];
__device__ float g_attw[B * S];
__device__ float g_bsum[FOURH];
__device__ float g_gatesw[(size_t)B * T * FOURH];     // row r=t*B+b
__device__ float g_encprojT[(size_t)FOURH * B * S];   // [n][b*S+s]
__device__ float g_gpart[(KSL + 1) * B * FOURH];
// bf16 hi/lo operand buffers
__device__ __nv_bfloat16 g_encHi[(size_t)B * S * TWOE];
__device__ __nv_bfloat16 g_encLo[(size_t)B * S * TWOE];
__device__ __nv_bfloat16 g_wrdHi[(size_t)B * T * E];  // row r=t*B+b
__device__ __nv_bfloat16 g_wrdLo[(size_t)B * T * E];
__device__ __nv_bfloat16 g_hsHi[(size_t)B * T * H];   // row r=b*T+t
__device__ __nv_bfloat16 g_hsLo[(size_t)B * T * H];
__device__ __nv_bfloat16 g_WoHi[(size_t)VT * H];
__device__ __nv_bfloat16 g_WoLo[(size_t)VT * H];
__device__ __nv_bfloat16 g_WcHi[(size_t)FOURH * H];   // W_ih[:,512:1536]
__device__ __nv_bfloat16 g_WcLo[(size_t)FOURH * H];
__device__ __nv_bfloat16 g_WwHi[(size_t)FOURH * E];   // W_ih[:,0:512]
__device__ __nv_bfloat16 g_WwLo[(size_t)FOURH * E];

// ---------------- asm helpers ----------------
__device__ __forceinline__ uint32_t s2u(const void* p) {
    uint32_t a;
    asm("{ .reg .u64 t; cvta.to.shared.u64 t, %1; cvt.u32.u64 %0, t; }" : "=r"(a) : "l"(p));
    return a;
}
__device__ __forceinline__ void cp16(uint32_t saddr, const void* g) {
    asm volatile("cp.async.cg.shared.global [%0], [%1], 16;" :: "r"(saddr), "l"(g));
}
__device__ __forceinline__ void cp_commit() {
    asm volatile("cp.async.commit_group;" ::: "memory");
}
__device__ __forceinline__ void cp_wait2() {
    asm volatile("cp.async.wait_group 2;" ::: "memory");
}
__device__ __forceinline__ void ldsm_x4(uint32_t* r, uint32_t addr) {
    asm volatile("ldmatrix.sync.aligned.m8n8.x4.shared.b16 {%0,%1,%2,%3}, [%4];"
                 : "=r"(r[0]), "=r"(r[1]), "=r"(r[2]), "=r"(r[3]) : "r"(addr));
}
__device__ __forceinline__ void ldsm_x2(uint32_t* r, uint32_t addr) {
    asm volatile("ldmatrix.sync.aligned.m8n8.x2.shared.b16 {%0,%1}, [%2];"
                 : "=r"(r[0]), "=r"(r[1]) : "r"(addr));
}
__device__ __forceinline__ void mma16816(float* d, const uint32_t* a, const uint32_t* b) {
    asm volatile("mma.sync.aligned.m16n8k16.row.col.f32.bf16.bf16.f32 "
                 "{%0,%1,%2,%3}, {%4,%5,%6,%7}, {%8,%9}, {%0,%1,%2,%3};"
                 : "+f"(d[0]), "+f"(d[1]), "+f"(d[2]), "+f"(d[3])
                 : "r"(a[0]), "r"(a[1]), "r"(a[2]), "r"(a[3]), "r"(b[0]), "r"(b[1]));
}
// 16B-segment offset (row r, seg c 0..3) in a 128x32-bf16 tile; conflict-free ldmatrix phases
__device__ __forceinline__ uint32_t swz(int r, int c) {
    return (uint32_t)(r * 64 + ((((c + (r >> 2)) & 3) ^ (r & 3)) << 4));
}
__device__ __forceinline__ float sigm(float x) { return 1.f / (1.f + expf(-x)); }

// ---------------- prep kernels ----------------

__global__ void __launch_bounds__(256) k_prep_enc(const int* __restrict__ src,
                                                  const int* __restrict__ pos,
                                                  const float* __restrict__ enc_emb,
                                                  const float* __restrict__ pos_emb) {
    int bs = blockIdx.x;
    int w = src[bs], p = pos[bs];
    int j = threadIdx.x * 4;
    const float* sp = (j < 512) ? (enc_emb + (size_t)w * E + j)
                                : (pos_emb + (size_t)p * E + (j - 512));
    float4 v = *(const float4*)sp;
    size_t o = (size_t)bs * TWOE + j;
    *(float4*)(g_enc + o) = v;
    float a[4]; a[0] = v.x; a[1] = v.y; a[2] = v.z; a[3] = v.w;
    __nv_bfloat16 h4[4], l4[4];
    #pragma unroll
    for (int i = 0; i < 4; i++) {
        __nv_bfloat16 bh = __float2bfloat16_rn(a[i]);
        h4[i] = bh;
        l4[i] = __float2bfloat16_rn(a[i] - __bfloat162float(bh));
    }
    *(uint2*)(g_encHi + o) = *(uint2*)h4;
    *(uint2*)(g_encLo + o) = *(uint2*)l4;
}

__global__ void __launch_bounds__(128) k_prep_words(const int* __restrict__ ts,
                                                    const float* __restrict__ dec_emb) {
    int r = blockIdx.x;
    int t = r / B, b = r % B;
    int w = ts[b * T + t];
    int j = threadIdx.x * 4;
    float4 v = *(const float4*)(dec_emb + (size_t)w * E + j);
    float a[4]; a[0] = v.x; a[1] = v.y; a[2] = v.z; a[3] = v.w;
    __nv_bfloat16 h4[4], l4[4];
    #pragma unroll
    for (int i = 0; i < 4; i++) {
        __nv_bfloat16 bh = __float2bfloat16_rn(a[i]);
        h4[i] = bh;
        l4[i] = __float2bfloat16_rn(a[i] - __bfloat162float(bh));
    }
    size_t o = (size_t)r * E + j;
    *(uint2*)(g_wrdHi + o) = *(uint2*)h4;
    *(uint2*)(g_wrdLo + o) = *(uint2*)l4;
}

// row converter, 8 elements per thread for ILP. threads = ncols/8.
__global__ void k_cvt_rows(const float* __restrict__ src, int srcStride,
                           __nv_bfloat16* __restrict__ hi, __nv_bfloat16* __restrict__ lo,
                           int ncols) {
    int r = blockIdx.x;
    int j = threadIdx.x * 8;
    const float* sp = src + (size_t)r * srcStride + j;
    float4 v0 = *(const float4*)sp;
    float4 v1 = *(const float4*)(sp + 4);
    float a[8];
    a[0] = v0.x; a[1] = v0.y; a[2] = v0.z; a[3] = v0.w;
    a[4] = v1.x; a[5] = v1.y; a[6] = v1.z; a[7] = v1.w;
    __nv_bfloat16 h8[8], l8[8];
    #pragma unroll
    for (int i = 0; i < 8; i++) {
        __nv_bfloat16 bh = __float2bfloat16_rn(a[i]);
        h8[i] = bh;
        l8[i] = __float2bfloat16_rn(a[i] - __bfloat162float(bh));
    }
    size_t o = (size_t)r * ncols + j;
    *(uint4*)(hi + o) = *(uint4*)h8;
    *(uint4*)(lo + o) = *(uint4*)l8;
}

__global__ void __launch_bounds__(256) k_bsum(const float* __restrict__ b_ih,
                                              const float* __restrict__ b_hh) {
    int i = blockIdx.x * 256 + threadIdx.x;
    g_bsum[i] = b_ih[i] + b_hh[i];
}

__global__ void __launch_bounds__(1024) k_encmean() {
    int b = blockIdx.x, d = threadIdx.x;
    float s = 0.f;
    const float* base = g_enc + (size_t)b * S * TWOE + d;
    #pragma unroll 8
    for (int i = 0; i < S; i++) s += base[(size_t)i * TWOE];
    g_encmean[b * TWOE + d] = s * (1.0f / S);
}

__global__ void __launch_bounds__(256) k_h0(const float* __restrict__ W_h0,
                                            const float* __restrict__ b_h0) {
    int gid = blockIdx.x * 8 + (threadIdx.x >> 5);
    int lane = threadIdx.x & 31;
    int b = gid >> 10, n = gid & 1023;
    const float* a = g_encmean + b * 1024;
    const float* w = W_h0 + (size_t)n * 1024;
    float acc = 0.f;
    for (int k = lane; k < 1024; k += 32) acc += a[k] * w[k];
    #pragma unroll
    for (int o = 16; o; o >>= 1) acc += __shfl_xor_sync(0xffffffffu, acc, o);
    if (lane == 0) {
        float v = acc + b_h0[n];
        g_h[b * H + n] = v;
        g_c[b * H + n] = v;
    }
}

// ---------------- bf16 HMMA 3-pass GEMM (R8 shape, 4-stage pipeline) ----------------
// CTA 128x128, 256 threads, BK=32. 4 stages x 32KB = 128KB smem, 1 CTA/SM.
// Issue of tile it+3 happens BEFORE compute of tile it (buffer (it+3)&3 freed last iter),
// overlapping cp.async with MMA.
#define PSTG 32768
#define HMMA_SMEM (4 * PSTG)

__global__ void __launch_bounds__(256, 1) k_hmma(
    const __nv_bfloat16* __restrict__ Ahi, const __nv_bfloat16* __restrict__ Alo,
    const __nv_bfloat16* __restrict__ Bhi, const __nv_bfloat16* __restrict__ Blo,
    const float* __restrict__ bias, float* __restrict__ C, int K, int ldc)
{
    extern __shared__ __align__(128) char smem[];
    const uint32_t sb = s2u(smem);
    int tid = threadIdx.x, lane = tid & 31, wid = tid >> 5;
    int wm = wid & 1, wn = wid >> 1;
    int m0 = blockIdx.x * 128;    // x fastest: consecutive CTAs share the B slice in L2
    int n0 = blockIdx.y * 128;
    int nIter = K >> 5;

    float acc[4][4][4];
    #pragma unroll
    for (int i = 0; i < 4; i++) {
        #pragma unroll
        for (int j = 0; j < 4; j++) {
            #pragma unroll
            for (int v = 0; v < 4; v++) acc[i][j][v] = 0.f;
        }
    }

    int lr = tid >> 2;
    int lc = tid & 3;
    uint32_t so0 = swz(lr, lc);
    uint32_t so1 = swz(lr + 64, lc);
    const char* gA0h = (const char*)(Ahi + (size_t)(m0 + lr) * K + lc * 8);
    const char* gA1h = (const char*)(Ahi + (size_t)(m0 + lr + 64) * K + lc * 8);
    const char* gA0l = (const char*)(Alo + (size_t)(m0 + lr) * K + lc * 8);
    const char* gA1l = (const char*)(Alo + (size_t)(m0 + lr + 64) * K + lc * 8);
    const char* gB0h = (const char*)(Bhi + (size_t)(n0 + lr) * K + lc * 8);
    const char* gB1h = (const char*)(Bhi + (size_t)(n0 + lr + 64) * K + lc * 8);
    const char* gB0l = (const char*)(Blo + (size_t)(n0 + lr) * K + lc * 8);
    const char* gB1l = (const char*)(Blo + (size_t)(n0 + lr + 64) * K + lc * 8);

    #define ISSUE(ST, K0) do { uint32_t s0 = sb + (uint32_t)(ST) * PSTG; \
        size_t kb = (size_t)(K0) * 2; \
        cp16(s0 + so0,          gA0h + kb); cp16(s0 + so1,          gA1h + kb); \
        cp16(s0 + 8192  + so0,  gA0l + kb); cp16(s0 + 8192  + so1,  gA1l + kb); \
        cp16(s0 + 16384 + so0,  gB0h + kb); cp16(s0 + 16384 + so1,  gB1h + kb); \
        cp16(s0 + 24576 + so0,  gB0l + kb); cp16(s0 + 24576 + so1,  gB1l + kb); } while (0)

    ISSUE(0, 0);  cp_commit();
    ISSUE(1, 32); cp_commit();
    ISSUE(2, 64); cp_commit();   // K >= 512 always

    int arow = lane & 15;
    int aselh = lane >> 4;
    int brow = lane & 7;
    int bselh = (lane >> 3) & 1;

    for (int it = 0; it < nIter; ++it) {
        cp_wait2();
        __syncthreads();
        // issue tile it+3 into buffer (it+3)&3 (freed at end of iteration it-1)
        if (it + 3 < nIter) ISSUE((it + 3) & 3, (it + 3) * 32);
        cp_commit();
        uint32_t stA_hi = sb + (uint32_t)(it & 3) * PSTG;
        uint32_t stA_lo = stA_hi + 8192;
        uint32_t stB_hi = stA_hi + 16384;
        uint32_t stB_lo = stA_hi + 24576;
        #pragma unroll
        for (int ks = 0; ks < 2; ++ks) {
            int c0 = ks * 2;
            uint32_t ah[4][4], al[4][4], bh[4][2], bl[4][2];
            #pragma unroll
            for (int mt = 0; mt < 4; mt++) {
                int r = wm * 64 + mt * 16 + arow;
                uint32_t off = swz(r, c0 + aselh);
                ldsm_x4(ah[mt], stA_hi + off);
                ldsm_x4(al[mt], stA_lo + off);
            }
            #pragma unroll
            for (int nt = 0; nt < 4; nt++) {
                int r = wn * 32 + nt * 8 + brow;
                uint32_t off = swz(r, c0 + bselh);
                ldsm_x2(bh[nt], stB_hi + off);
                ldsm_x2(bl[nt], stB_lo + off);
            }
            #pragma unroll
            for (int mt = 0; mt < 4; mt++) {
                #pragma unroll
                for (int nt = 0; nt < 4; nt++) {
                    mma16816(acc[mt][nt], ah[mt], bh[nt]);
                    mma16816(acc[mt][nt], ah[mt], bl[nt]);
                    mma16816(acc[mt][nt], al[mt], bh[nt]);
                }
            }
        }
        __syncthreads();   // buffer (it+4)&3 == it&3 reused by next iteration's ISSUE
    }
    #undef ISSUE

    #pragma unroll
    for (int nt = 0; nt < 4; nt++) {
        int col = n0 + wn * 32 + nt * 8 + (lane & 3) * 2;
        float b0 = 0.f, b1 = 0.f;
        if (bias) { b0 = bias[col]; b1 = bias[col + 1]; }
        #pragma unroll
        for (int mt = 0; mt < 4; mt++) {
            int row = m0 + wm * 64 + mt * 16 + (lane >> 2);
            float* c0p = C + (size_t)row * ldc + col;
            float* c1p = C + (size_t)(row + 8) * ldc + col;
            c0p[0] = acc[mt][nt][0] + b0;
            c0p[1] = acc[mt][nt][1] + b1;
            c1p[0] = acc[mt][nt][2] + b0;
            c1p[1] = acc[mt][nt][3] + b1;
        }
    }
}

// ---------------- per-step kernels (R8 structure) ----------------

__global__ void __launch_bounds__(256) k_gatesh(const float* __restrict__ W_hh) {
    int slice = blockIdx.y;
    int tid = threadIdx.x;

    if (slice >= KSL) {
        int b = blockIdx.x;
        int n0 = (slice - KSL) * 512;
        __shared__ float aw[S];
        if (tid < S) aw[tid] = g_attw[b * S + tid];
        __syncthreads();
        float* gp = g_gpart + (size_t)KSL * (B * FOURH) + (size_t)b * FOURH;
        #pragma unroll
        for (int half = 0; half < 2; half++) {
            int n = n0 + half * 256 + tid;
            const float4* ep = (const float4*)(g_encprojT + (size_t)n * (B * S) + b * S);
            float acc = 0.f;
            #pragma unroll
            for (int s4 = 0; s4 < 16; s4++) {
                float4 v = ep[s4];
                acc += aw[s4 * 4 + 0] * v.x + aw[s4 * 4 + 1] * v.y
                     + aw[s4 * 4 + 2] * v.z + aw[s4 * 4 + 3] * v.w;
            }
            gp[n] = acc;
        }
        return;
    }

    const int KC = 32;
    __shared__ float Xs[KC][36];
    __shared__ float Ws[KC][132];
    int n0 = blockIdx.x * 128;
    int k00 = slice * 256;
    int mg = tid >> 5;
    int ng = tid & 31;

    float acc[4][4];
    #pragma unroll
    for (int i = 0; i < 4; i++) {
        #pragma unroll
        for (int j = 0; j < 4; j++) acc[i][j] = 0.f;
    }

    int xr = tid >> 3;
    int xk = (tid & 7) << 2;

    for (int kc = k00; kc < k00 + 256; kc += KC) {
        float4 xv = *(const float4*)(g_h + (size_t)xr * H + kc + xk);
        float4 wv[4];
        #pragma unroll
        for (int p = 0; p < 4; p++) {
            int row = n0 + p * 32 + xr;
            wv[p] = *(const float4*)(W_hh + (size_t)row * H + kc + xk);
        }
        __syncthreads();
        Xs[xk + 0][xr] = xv.x; Xs[xk + 1][xr] = xv.y;
        Xs[xk + 2][xr] = xv.z; Xs[xk + 3][xr] = xv.w;
        #pragma unroll
        for (int p = 0; p < 4; p++) {
            Ws[xk + 0][p * 32 + xr] = wv[p].x;
            Ws[xk + 1][p * 32 + xr] = wv[p].y;
            Ws[xk + 2][p * 32 + xr] = wv[p].z;
            Ws[xk + 3][p * 32 + xr] = wv[p].w;
        }
        __syncthreads();
        #pragma unroll 8
        for (int kk = 0; kk < KC; kk++) {
            float xa[4], wf[4];
            *(float4*)xa = *(const float4*)&Xs[kk][mg * 4];
            *(float4*)wf = *(const float4*)&Ws[kk][ng * 4];
            #pragma unroll
            for (int i = 0; i < 4; i++) {
                #pragma unroll
                for (int j = 0; j < 4; j++)
                    acc[i][j] += xa[i] * wf[j];
            }
        }
    }
    float* gp = g_gpart + (size_t)slice * (B * FOURH);
    #pragma unroll
    for (int i = 0; i < 4; i++) {
        int m = mg * 4 + i;
        #pragma unroll
        for (int j = 0; j < 4; j++) {
            int n = n0 + ng * 4 + j;
            gp[(size_t)m * FOURH + n] = acc[i][j];
        }
    }
}

// fused LSTM pointwise (t>=0) + attention for next step. grid 32 (b), 1024 threads.
__global__ void __launch_bounds__(1024) k_lstm_attn(int t, const int* __restrict__ source_lengths) {
    int b = blockIdx.x;
    int n = threadIdx.x;
    __shared__ float sh[1024];
    __shared__ float se[64];

    if (t >= 0) {
        const float* gw = g_gatesw + ((size_t)t * B + b) * FOURH;
        float gi = gw[n], gf = gw[n + 1024], gg = gw[n + 2048], go = gw[n + 3072];
        #pragma unroll
        for (int s = 0; s < KSL + 1; s++) {
            const float* gp = g_gpart + (size_t)s * (B * FOURH) + (size_t)b * FOURH;
            gi += gp[n]; gf += gp[n + 1024]; gg += gp[n + 2048]; go += gp[n + 3072];
        }
        float c = g_c[b * H + n];
        float iv = sigm(gi), fv = sigm(gf), gv = tanhf(gg), ov = sigm(go);
        c = fv * c + iv * gv;
        float h = ov * tanhf(c);
        g_c[b * H + n] = c;
        g_h[b * H + n] = h;
        sh[n] = h;
        size_t row = ((size_t)b * T + t) * H + n;
        __nv_bfloat16 hh = __float2bfloat16_rn(h);
        g_hsHi[row] = hh;
        g_hsLo[row] = __float2bfloat16_rn(h - __bfloat162float(hh));
    } else {
        sh[n] = g_h[b * H + n];
    }
    __syncthreads();

    int warp = n >> 5, lane = n & 31;
    #pragma unroll
    for (int q = 0; q < 2; q++) {
        int s = warp * 2 + q;
        const float* er = g_enc + ((size_t)b * S + s) * TWOE;
        float acc = 0.f;
        #pragma unroll 8
        for (int k = lane; k < TWOE; k += 32) acc += er[k] * sh[k];
        #pragma unroll
        for (int o = 16; o; o >>= 1) acc += __shfl_xor_sync(0xffffffffu, acc, o);
        if (lane == 0) se[s] = acc;
    }
    __syncthreads();
    if (warp == 0) {
        int len = source_lengths[b];
        float e0 = se[lane], e1 = se[lane + 32];
        float m = fmaxf(e0, e1);
        #pragma unroll
        for (int o = 16; o; o >>= 1) m = fmaxf(m, __shfl_xor_sync(0xffffffffu, m, o));
        float p0 = (lane < len)      ? expf(e0 - m) : 0.f;
        float p1 = (lane + 32 < len) ? expf(e1 - m) : 0.f;
        float ssum = p0 + p1;
        #pragma unroll
        for (int o = 16; o; o >>= 1) ssum += __shfl_xor_sync(0xffffffffu, ssum, o);
        float inv = 1.f / ssum;
        g_attw[b * S + lane] = p0 * inv;
        g_attw[b * S + lane + 32] = p1 * inv;
    }
}

// ---------------- host ----------------
extern "C" void kernel_launch(void* const* d_in, const int* in_sizes, int n_in,
                              void* d_out, int out_size) {
    int p = 0;
    auto nx = [&]() -> const void* {
        while (p < n_in && in_sizes[p] == 1) p++;
        return d_in[p++];
    };
    const int*   ts      = (const int*)nx();
    (void)nx();                                  // target_lengths (unused)
    const int*   sl      = (const int*)nx();
    const int*   ss      = (const int*)nx();
    const int*   pos     = (const int*)nx();
    const float* enc_emb = (const float*)nx();
    const float* pos_emb = (const float*)nx();
    const float* dec_emb = (const float*)nx();
    const float* W_h0    = (const float*)nx();
    const float* b_h0    = (const float*)nx();
    const float* W_ih    = (const float*)nx();
    const float* W_hh    = (const float*)nx();
    const float* b_ih    = (const float*)nx();
    const float* b_hh    = (const float*)nx();
    const float* W_out   = (const float*)nx();
    const float* b_out   = (const float*)nx();

    float *p_gatesw, *p_encprojT, *p_bsum;
    __nv_bfloat16 *p_encHi, *p_encLo, *p_wrdHi, *p_wrdLo, *p_hsHi, *p_hsLo;
    __nv_bfloat16 *p_WoHi, *p_WoLo, *p_WcHi, *p_WcLo, *p_WwHi, *p_WwLo;
    cudaGetSymbolAddress((void**)&p_gatesw,   g_gatesw);
    cudaGetSymbolAddress((void**)&p_encprojT, g_encprojT);
    cudaGetSymbolAddress((void**)&p_bsum,     g_bsum);
    cudaGetSymbolAddress((void**)&p_encHi,    g_encHi);
    cudaGetSymbolAddress((void**)&p_encLo,    g_encLo);
    cudaGetSymbolAddress((void**)&p_wrdHi,    g_wrdHi);
    cudaGetSymbolAddress((void**)&p_wrdLo,    g_wrdLo);
    cudaGetSymbolAddress((void**)&p_hsHi,     g_hsHi);
    cudaGetSymbolAddress((void**)&p_hsLo,     g_hsLo);
    cudaGetSymbolAddress((void**)&p_WoHi,     g_WoHi);
    cudaGetSymbolAddress((void**)&p_WoLo,     g_WoLo);
    cudaGetSymbolAddress((void**)&p_WcHi,     g_WcHi);
    cudaGetSymbolAddress((void**)&p_WcLo,     g_WcLo);
    cudaGetSymbolAddress((void**)&p_WwHi,     g_WwHi);
    cudaGetSymbolAddress((void**)&p_WwLo,     g_WwLo);

    cudaFuncSetAttribute(k_hmma, cudaFuncAttributeMaxDynamicSharedMemorySize, HMMA_SMEM);

    // ---- prep ----
    k_prep_enc  <<<B * S, 256>>>(ss, pos, enc_emb, pos_emb);
    k_prep_words<<<B * T, 128>>>(ts, dec_emb);
    k_cvt_rows  <<<VT, H / 8>>>(W_out, H, p_WoHi, p_WoLo, H);
    k_cvt_rows  <<<FOURH, H / 8>>>(W_ih + 512, 1536, p_WcHi, p_WcLo, H);
    k_cvt_rows  <<<FOURH, E / 8>>>(W_ih, 1536, p_WwHi, p_WwLo, E);
    k_bsum      <<<FOURH / 256, 256>>>(b_ih, b_hh);
    k_encmean   <<<B, 1024>>>();
    k_h0        <<<(B * H) / 8, 256>>>(W_h0, b_h0);
    // gates_w = words @ W_ih[:,:512]^T + (b_ih + b_hh)    [2048 x 4096], K=512
    k_hmma<<<dim3(16, FOURH / 128), 256, HMMA_SMEM>>>(
        p_wrdHi, p_wrdLo, p_WwHi, p_WwLo, p_bsum, p_gatesw, E, FOURH);
    // encprojT[n][bs] = W_ctx @ enc^T    [4096 x 2048], K=1024
    k_hmma<<<dim3(FOURH / 128, 16), 256, HMMA_SMEM>>>(
        p_WcHi, p_WcLo, p_encHi, p_encLo, nullptr, p_encprojT, H, B * S);
    // initial attention from h0
    k_lstm_attn<<<B, 1024>>>(-1, sl);

    // ---- sequential phase: 2 launches per step ----
    for (int t = 0; t < T; t++) {
        k_gatesh   <<<dim3(32, KSL + 8), 256>>>(W_hh);
        k_lstm_attn<<<B, 1024>>>(t, sl);
    }

    // ---- output projection: hs @ W_out^T + b_out   [2048 x 32000], K=1024 ----
    k_hmma<<<dim3(16, VT / 128), 256, HMMA_SMEM>>>(
        p_hsHi, p_hsLo, p_WoHi, p_WoLo, b_out, (float*)d_out, H, VT);
}